// round 4
// baseline (speedup 1.0000x reference)
#include <cuda_runtime.h>

// Problem constants
#define BATCH   1024
#define TSTEPS  256
#define UNITS   256
#define G4      1024   // 4*UNITS
#define NC      128    // num chars
#define TB      8      // batch rows per CTA
#define NCTA    (BATCH / TB)     // 128 CTAs
#define NTHREADS 256

// padded smem pitches (avoid bank conflicts, keep 8B alignment for paired loads)
#define ZPITCH  10     // z_s[1024][10] floats
#define HPITCH  10     // h_s[256][10] floats

#define Z_FLOATS (G4 * ZPITCH)       // 10240
#define H_FLOATS (UNITS * HPITCH)    // 2560
#define SMEM_BYTES ((Z_FLOATS + H_FLOATS) * 4)  // 51200 B (> 48KB static limit -> dynamic)

// ---- packed fp32x2 helpers (Blackwell native dual-fp32 path) ----
__device__ __forceinline__ unsigned long long pack_dup(float x) {
    unsigned long long r;
    asm("mov.b64 %0, {%1, %1};" : "=l"(r) : "f"(x));
    return r;
}
__device__ __forceinline__ unsigned long long pack2(float lo, float hi) {
    unsigned long long r;
    asm("mov.b64 %0, {%1, %2};" : "=l"(r) : "f"(lo), "f"(hi));
    return r;
}
__device__ __forceinline__ void ffma2(unsigned long long& d,
                                      unsigned long long a,
                                      unsigned long long b) {
    asm("fma.rn.f32x2 %0, %1, %2, %0;" : "+l"(d) : "l"(a), "l"(b));
}

// ---- numerically safe fast activations ----
__device__ __forceinline__ float sigmoid_f(float x) {
    // x << 0: expf(-x) -> inf, 1/inf -> 0 (correct). x >> 0: e -> 0 -> 1 (correct).
    float e = __expf(-x);
    return __fdividef(1.0f, 1.0f + e);
}
__device__ __forceinline__ float tanh_f(float x) {
    // robust form: never overflows (e in (0,1])
    float a = fabsf(x);
    float e = __expf(-2.0f * a);
    float t = 1.0f - __fdividef(2.0f * e, 1.0f + e);
    return copysignf(t, x);
}

__global__ __launch_bounds__(NTHREADS, 1)
void lstm_char_rnn_kernel(const int*   __restrict__ inp,   // [1024,256] int32
                          const float* __restrict__ Wk,    // kernel [128,1024]
                          const float* __restrict__ R,     // recurrent [256,1024]
                          const float* __restrict__ bias,  // [1024]
                          const float* __restrict__ Dw,    // dense_w [256,128]
                          const float* __restrict__ Db,    // dense_b [128]
                          float*       __restrict__ out)   // [1024,128]
{
    extern __shared__ float sm[];
    float* z_s = sm;                 // [1024][ZPITCH] (reused as logits at the end)
    float* h_s = sm + Z_FLOATS;      // [256][HPITCH]; h_s[u][r] = h of unit u, local row r

    const int t  = threadIdx.x;      // 0..255
    const int b0 = blockIdx.x * TB;  // this CTA's batch rows [b0, b0+8)
    const int j0 = t * 4;            // this thread's 4 z-columns

    // zero the h state
    for (int i = t; i < H_FLOATS; i += NTHREADS) h_s[i] = 0.0f;

    // per-thread gate biases: thread t owns unit u = t
    const float bi_ = bias[t];
    const float bf_ = bias[UNITS + t];
    const float bg_ = bias[2 * UNITS + t];
    const float bo_ = bias[3 * UNITS + t];

    float c[TB];
#pragma unroll
    for (int r = 0; r < TB; r++) c[r] = 0.0f;

    __syncthreads();

    const float4* Rp = reinterpret_cast<const float4*>(R) + t;  // row stride = 256 float4

    for (int step = 0; step < TSTEPS; step++) {
        // ================= matvec phase: z[b][j0..j0+3], b in [b0..b0+7] ============
        // acc[p][q]: f32x2 holding (z[row 2p], z[row 2p+1]) at column j0+q
        unsigned long long acc[4][4];

        // init z = x_proj = kernel[input[b][step]] (bias folded into gate phase)
#pragma unroll
        for (int p = 0; p < 4; p++) {
            int v0 = __ldg(&inp[(b0 + 2 * p)     * TSTEPS + step]);
            int v1 = __ldg(&inp[(b0 + 2 * p + 1) * TSTEPS + step]);
            float4 x0 = __ldg(reinterpret_cast<const float4*>(&Wk[v0 * G4 + j0]));
            float4 x1 = __ldg(reinterpret_cast<const float4*>(&Wk[v1 * G4 + j0]));
            acc[p][0] = pack2(x0.x, x1.x);
            acc[p][1] = pack2(x0.y, x1.y);
            acc[p][2] = pack2(x0.z, x1.z);
            acc[p][3] = pack2(x0.w, x1.w);
        }

        // K-loop: stream R from L2, h row-pairs from SMEM (broadcast, conflict-free)
#pragma unroll 8
        for (int k = 0; k < UNITS; k++) {
            float4 rv = __ldg(&Rp[k * (G4 / 4)]);   // R[k][j0..j0+3]
            unsigned long long rd0 = pack_dup(rv.x);
            unsigned long long rd1 = pack_dup(rv.y);
            unsigned long long rd2 = pack_dup(rv.z);
            unsigned long long rd3 = pack_dup(rv.w);
            const float* hk = &h_s[k * HPITCH];
#pragma unroll
            for (int p = 0; p < 4; p++) {
                unsigned long long hp =
                    *reinterpret_cast<const unsigned long long*>(&hk[2 * p]);
                ffma2(acc[p][0], hp, rd0);
                ffma2(acc[p][1], hp, rd1);
                ffma2(acc[p][2], hp, rd2);
                ffma2(acc[p][3], hp, rd3);
            }
        }

        // write z pairs to smem: z_s[col][rowpair]
#pragma unroll
        for (int q = 0; q < 4; q++) {
            int j = j0 + q;
#pragma unroll
            for (int p = 0; p < 4; p++) {
                *reinterpret_cast<unsigned long long*>(&z_s[j * ZPITCH + 2 * p]) =
                    acc[p][q];
            }
        }
        __syncthreads();

        // ================= gate phase: thread t owns unit u = t, all 8 rows =========
#pragma unroll
        for (int r = 0; r < TB; r++) {
            float zi = z_s[t               * ZPITCH + r] + bi_;
            float zf = z_s[(UNITS     + t) * ZPITCH + r] + bf_;
            float zg = z_s[(2 * UNITS + t) * ZPITCH + r] + bg_;
            float zo = z_s[(3 * UNITS + t) * ZPITCH + r] + bo_;
            float ig = sigmoid_f(zi);
            float fg = sigmoid_f(zf);
            float gg = tanh_f(zg);
            float og = sigmoid_f(zo);
            float cn = fg * c[r] + ig * gg;
            c[r] = cn;
            h_s[t * HPITCH + r] = og * tanh_f(cn);
        }
        __syncthreads();
    }

    // ================= dense: logits[r][col] = h_last[r] @ Dw + Db ==================
    if (t < NC) {
        float lg[TB];
#pragma unroll
        for (int r = 0; r < TB; r++) lg[r] = Db[t];
        for (int u = 0; u < UNITS; u++) {
            float w = __ldg(&Dw[u * NC + t]);
            const float* hk = &h_s[u * HPITCH];
#pragma unroll
            for (int r = 0; r < TB; r++) lg[r] = fmaf(hk[r], w, lg[r]);
        }
#pragma unroll
        for (int r = 0; r < TB; r++) z_s[r * NC + t] = lg[r];
    }
    __syncthreads();

    // ================= softmax: warp w handles local row w ==========================
    const int w    = t >> 5;
    const int lane = t & 31;
    float v[4];
    float mx = -3.0e38f;
#pragma unroll
    for (int q = 0; q < 4; q++) {
        v[q] = z_s[w * NC + lane + 32 * q];
        mx = fmaxf(mx, v[q]);
    }
#pragma unroll
    for (int off = 16; off >= 1; off >>= 1)
        mx = fmaxf(mx, __shfl_xor_sync(0xffffffffu, mx, off));
    float sum = 0.0f;
#pragma unroll
    for (int q = 0; q < 4; q++) { v[q] = __expf(v[q] - mx); sum += v[q]; }
#pragma unroll
    for (int off = 16; off >= 1; off >>= 1)
        sum += __shfl_xor_sync(0xffffffffu, sum, off);
    float inv = 1.0f / sum;
#pragma unroll
    for (int q = 0; q < 4; q++)
        out[(b0 + w) * NC + lane + 32 * q] = v[q] * inv;
}

extern "C" void kernel_launch(void* const* d_in, const int* in_sizes, int n_in,
                              void* d_out, int out_size) {
    const int*   inp  = (const int*)  d_in[0];  // inputs [1024,256]
    const float* Wk   = (const float*)d_in[1];  // kernel [128,1024]
    const float* R    = (const float*)d_in[2];  // recurrent_kernel [256,1024]
    const float* bias = (const float*)d_in[3];  // bias [1024]
    const float* Dw   = (const float*)d_in[4];  // dense_w [256,128]
    const float* Db   = (const float*)d_in[5];  // dense_b [128]
    float*       out  = (float*)d_out;          // [1024,128]

    // dynamic smem > 48KB: opt in (idempotent, cheap; legal outside stream ops)
    cudaFuncSetAttribute(lstm_char_rnn_kernel,
                         cudaFuncAttributeMaxDynamicSharedMemorySize, SMEM_BYTES);

    lstm_char_rnn_kernel<<<NCTA, NTHREADS, SMEM_BYTES>>>(inp, Wk, R, bias, Dw, Db, out);
}

// round 6
// speedup vs baseline: 1.0253x; 1.0253x over previous
#include <cuda_runtime.h>

// Problem constants
#define BATCH   1024
#define TSTEPS  256
#define UNITS   256
#define G4      1024   // 4*UNITS
#define NC      128    // num chars
#define TB      8      // batch rows per CTA
#define NCTA    (BATCH / TB)     // 128 CTAs
#define NTHREADS 512             // 16 warps -> 4 warps/SMSP

// smem pitches
#define ZP  10     // z_s[1024][10] floats (8B-aligned pairs, odd-ish stride vs banks)
#define HP  12     // h_s[256][12] floats (16B-aligned rows for LDS.128)

#define Z_FLOATS (G4 * ZP)        // 10240
#define H_FLOATS (UNITS * HP)     // 3072
#define SMEM_BYTES ((Z_FLOATS + H_FLOATS) * 4)   // 53248 B -> dynamic smem

// ---- packed fp32x2 helpers ----
__device__ __forceinline__ unsigned long long pack_dup(float x) {
    unsigned long long r;
    asm("mov.b64 %0, {%1, %1};" : "=l"(r) : "f"(x));
    return r;
}
__device__ __forceinline__ unsigned long long pack2(float lo, float hi) {
    unsigned long long r;
    asm("mov.b64 %0, {%1, %2};" : "=l"(r) : "f"(lo), "f"(hi));
    return r;
}
__device__ __forceinline__ void unpack2(unsigned long long v, float& lo, float& hi) {
    asm("mov.b64 {%0, %1}, %2;" : "=f"(lo), "=f"(hi) : "l"(v));
}
__device__ __forceinline__ void ffma2(unsigned long long& d,
                                      unsigned long long a,
                                      unsigned long long b) {
    asm("fma.rn.f32x2 %0, %1, %2, %0;" : "+l"(d) : "l"(a), "l"(b));
}

// ---- numerically safe fast activations (identical to R3-passing version) ----
__device__ __forceinline__ float sigmoid_f(float x) {
    float e = __expf(-x);
    return __fdividef(1.0f, 1.0f + e);
}
__device__ __forceinline__ float tanh_f(float x) {
    float a = fabsf(x);
    float e = __expf(-2.0f * a);
    float t = 1.0f - __fdividef(2.0f * e, 1.0f + e);
    return copysignf(t, x);
}

__global__ __launch_bounds__(NTHREADS, 1)
void lstm_char_rnn_kernel(const int*   __restrict__ inp,   // [1024,256] int32
                          const float* __restrict__ Wk,    // kernel [128,1024]
                          const float* __restrict__ R,     // recurrent [256,1024]
                          const float* __restrict__ bias,  // [1024]
                          const float* __restrict__ Dw,    // dense_w [256,128]
                          const float* __restrict__ Db,    // dense_b [128]
                          float*       __restrict__ out)   // [1024,128]
{
    extern __shared__ float sm[];
    float* z_s = sm;                 // [1024][ZP]  (reused for logits at the end)
    float* h_s = sm + Z_FLOATS;      // [256][HP]; h_s[u*HP + r] = h(unit u, local row r)

    const int t  = threadIdx.x;      // 0..511
    const int b0 = blockIdx.x * TB;  // this CTA's batch rows [b0, b0+8)
    const int j0 = 2 * t;            // this thread's 2 z-columns

    // zero the h state
    for (int i = t; i < H_FLOATS; i += NTHREADS) h_s[i] = 0.0f;

    // gate-phase ownership: thread t owns unit u = t>>1, rows r0..r0+3
    const int u  = t >> 1;
    const int r0 = 4 * (t & 1);
    const float bi_ = bias[u];
    const float bf_ = bias[UNITS + u];
    const float bg_ = bias[2 * UNITS + u];
    const float bo_ = bias[3 * UNITS + u];

    float c[4];
#pragma unroll
    for (int j = 0; j < 4; j++) c[j] = 0.0f;

    __syncthreads();

    const float2* Rp = reinterpret_cast<const float2*>(R) + t;  // row stride = 512 float2

    for (int step = 0; step < TSTEPS; step++) {
        // ========== matvec: z[b][j0..j0+1], b in [b0..b0+7] ==========
        // acc[p][q]: f32x2 = (z[row 2p], z[row 2p+1]) at column j0+q
        unsigned long long acc[4][2];

        // init z = x_proj = kernel[input[b][step]]
#pragma unroll
        for (int p = 0; p < 4; p++) {
            int v0 = __ldg(&inp[(b0 + 2 * p)     * TSTEPS + step]);
            int v1 = __ldg(&inp[(b0 + 2 * p + 1) * TSTEPS + step]);
            float2 x0 = __ldg(reinterpret_cast<const float2*>(&Wk[v0 * G4 + j0]));
            float2 x1 = __ldg(reinterpret_cast<const float2*>(&Wk[v1 * G4 + j0]));
            acc[p][0] = pack2(x0.x, x1.x);
            acc[p][1] = pack2(x0.y, x1.y);
        }

        // K-loop: R streamed from L1/L2, h row-pairs broadcast from SMEM
#pragma unroll 8
        for (int k = 0; k < UNITS; k++) {
            float2 rv = __ldg(&Rp[k * (G4 / 2)]);   // R[k][j0..j0+1]
            unsigned long long rd0 = pack_dup(rv.x);
            unsigned long long rd1 = pack_dup(rv.y);
            // rows (0,1),(2,3) and (4,5),(6,7) as two LDS.128
            ulonglong2 hA = *reinterpret_cast<const ulonglong2*>(&h_s[k * HP]);
            ulonglong2 hB = *reinterpret_cast<const ulonglong2*>(&h_s[k * HP + 4]);
            ffma2(acc[0][0], hA.x, rd0);  ffma2(acc[0][1], hA.x, rd1);
            ffma2(acc[1][0], hA.y, rd0);  ffma2(acc[1][1], hA.y, rd1);
            ffma2(acc[2][0], hB.x, rd0);  ffma2(acc[2][1], hB.x, rd1);
            ffma2(acc[3][0], hB.y, rd0);  ffma2(acc[3][1], hB.y, rd1);
        }

        // write z pairs to smem: z_s[col][row]
#pragma unroll
        for (int q = 0; q < 2; q++) {
#pragma unroll
            for (int p = 0; p < 4; p++) {
                *reinterpret_cast<unsigned long long*>(&z_s[(j0 + q) * ZP + 2 * p]) =
                    acc[p][q];
            }
        }
        __syncthreads();

        // ========== gates: thread owns unit u, rows r0..r0+3 ==========
        float hv[4];
#pragma unroll
        for (int j = 0; j < 4; j++) {
            int r = r0 + j;
            float zi = z_s[u               * ZP + r] + bi_;
            float zf = z_s[(UNITS     + u) * ZP + r] + bf_;
            float zg = z_s[(2 * UNITS + u) * ZP + r] + bg_;
            float zo = z_s[(3 * UNITS + u) * ZP + r] + bo_;
            float ig = sigmoid_f(zi);
            float fg = sigmoid_f(zf);
            float gg = tanh_f(zg);
            float og = sigmoid_f(zo);
            float cn = fg * c[j] + ig * gg;
            c[j] = cn;
            hv[j] = og * tanh_f(cn);
        }
        // one STS.128 (16B aligned: byte offset = 48*u + 16*(t&1))
        *reinterpret_cast<float4*>(&h_s[u * HP + r0]) =
            make_float4(hv[0], hv[1], hv[2], hv[3]);
        __syncthreads();
    }

    // ========== dense: logits[r][col] = h_last[r] @ Dw + Db ==========
    {
        const int jc = t & (NC - 1);     // 0..127 output column
        const int rp = t >> 7;           // 0..3 row pair
        unsigned long long lg = pack_dup(__ldg(&Db[jc]));
        for (int uu = 0; uu < UNITS; uu++) {
            unsigned long long hp =
                *reinterpret_cast<const unsigned long long*>(&h_s[uu * HP + 2 * rp]);
            ffma2(lg, hp, pack_dup(__ldg(&Dw[uu * NC + jc])));
        }
        float l0, l1;
        unpack2(lg, l0, l1);
        z_s[(2 * rp)     * NC + jc] = l0;
        z_s[(2 * rp + 1) * NC + jc] = l1;
    }
    __syncthreads();

    // ========== softmax: first 8 warps, warp w handles local row w ==========
    if (t < 256) {
        const int w    = t >> 5;
        const int lane = t & 31;
        float v[4];
        float mx = -3.0e38f;
#pragma unroll
        for (int q = 0; q < 4; q++) {
            v[q] = z_s[w * NC + lane + 32 * q];
            mx = fmaxf(mx, v[q]);
        }
#pragma unroll
        for (int off = 16; off >= 1; off >>= 1)
            mx = fmaxf(mx, __shfl_xor_sync(0xffffffffu, mx, off));
        float sum = 0.0f;
#pragma unroll
        for (int q = 0; q < 4; q++) { v[q] = __expf(v[q] - mx); sum += v[q]; }
#pragma unroll
        for (int off = 16; off >= 1; off >>= 1)
            sum += __shfl_xor_sync(0xffffffffu, sum, off);
        float inv = 1.0f / sum;
#pragma unroll
        for (int q = 0; q < 4; q++)
            out[(b0 + w) * NC + lane + 32 * q] = v[q] * inv;
    }
}

extern "C" void kernel_launch(void* const* d_in, const int* in_sizes, int n_in,
                              void* d_out, int out_size) {
    const int*   inp  = (const int*)  d_in[0];  // inputs [1024,256]
    const float* Wk   = (const float*)d_in[1];  // kernel [128,1024]
    const float* R    = (const float*)d_in[2];  // recurrent_kernel [256,1024]
    const float* bias = (const float*)d_in[3];  // bias [1024]
    const float* Dw   = (const float*)d_in[4];  // dense_w [256,128]
    const float* Db   = (const float*)d_in[5];  // dense_b [128]
    float*       out  = (float*)d_out;          // [1024,128]

    cudaFuncSetAttribute(lstm_char_rnn_kernel,
                         cudaFuncAttributeMaxDynamicSharedMemorySize, SMEM_BYTES);

    lstm_char_rnn_kernel<<<NCTA, NTHREADS, SMEM_BYTES>>>(inp, Wk, R, bias, Dw, Db, out);
}